// round 4
// baseline (speedup 1.0000x reference)
#include <cuda_runtime.h>
#include <math.h>

// Problem constants (fixed by the dataset)
#define NN 50000
#define NE 800000

// ---------------- device scratch (no allocation allowed) ----------------
__device__ float g_FT[NN * 128];   // per-layer transformed features [N, H*64]
__device__ float g_X[NN * 128];    // layer activations ping buffer  [N, H*64]
__device__ float g_A1[NN * 2];     // dst-side attention logits [N, H]
__device__ float g_A2[NN * 2];     // src-side attention logits [N, H]
__device__ int   g_deg[NN];
__device__ int   g_rowptr[NN + 1];
__device__ int   g_ptmp[NN];
__device__ int   g_csrc[NE];       // CSR (by dst) storing src node ids

// ---------------- packed f32x2 helpers (Blackwell FFMA2 path) ----------------
__device__ __forceinline__ unsigned long long fma2(unsigned long long a,
                                                   unsigned long long b,
                                                   unsigned long long c) {
    unsigned long long d;
    asm("fma.rn.f32x2 %0, %1, %2, %3;" : "=l"(d) : "l"(a), "l"(b), "l"(c));
    return d;
}
__device__ __forceinline__ unsigned long long pack2(float x) {
    unsigned long long d;
    asm("mov.b64 %0, {%1, %1};" : "=l"(d) : "r"(__float_as_uint(x)));
    return d;
}

// ---------------- CSR build ----------------
__global__ void k_zero_deg() {
    int i = blockIdx.x * blockDim.x + threadIdx.x;
    if (i < NN) g_deg[i] = 0;
}

__global__ void k_count(const int* __restrict__ dst) {
    int e = blockIdx.x * blockDim.x + threadIdx.x;
    if (e < NE) atomicAdd(&g_deg[dst[e]], 1);
}

// single-block exclusive scan over g_deg -> g_rowptr / g_ptmp
// thread-coarsened: 16 elements per thread -> 4 outer iterations total.
__global__ void k_scan() {
    __shared__ int warp_tot[32];
    __shared__ int warp_pref[32];
    __shared__ int s_total;
    __shared__ int s_carry;
    const int VPT = 16;
    int tid = threadIdx.x, lane = tid & 31, wid = tid >> 5;
    if (tid == 0) { s_carry = 0; g_rowptr[0] = 0; }
    __syncthreads();
    for (int base = 0; base < NN; base += 1024 * VPT) {
        int i0 = base + tid * VPT;
        int v[VPT];
        int sum = 0;
        #pragma unroll
        for (int j = 0; j < VPT; j++) {
            v[j] = (i0 + j < NN) ? g_deg[i0 + j] : 0;
            sum += v[j];
        }
        // warp inclusive scan of per-thread sums
        int x = sum;
        #pragma unroll
        for (int off = 1; off < 32; off <<= 1) {
            int t = __shfl_up_sync(0xffffffffu, x, off);
            if (lane >= off) x += t;
        }
        if (lane == 31) warp_tot[wid] = x;
        __syncthreads();
        if (wid == 0) {
            int w = warp_tot[lane];
            int y = w;
            #pragma unroll
            for (int off = 1; off < 32; off <<= 1) {
                int t = __shfl_up_sync(0xffffffffu, y, off);
                if (lane >= off) y += t;
            }
            warp_pref[lane] = y - w;
            if (lane == 31) s_total = y;
        }
        __syncthreads();
        int run = s_carry + warp_pref[wid] + (x - sum);  // exclusive start of this thread
        #pragma unroll
        for (int j = 0; j < VPT; j++) {
            if (i0 + j < NN) {
                g_ptmp[i0 + j] = run;
                run += v[j];
                g_rowptr[i0 + j + 1] = run;
            }
        }
        __syncthreads();
        if (tid == 0) s_carry += s_total;
        __syncthreads();
    }
}

__global__ void k_scatter(const int* __restrict__ src, const int* __restrict__ dst) {
    int e = blockIdx.x * blockDim.x + threadIdx.x;
    if (e < NE) {
        int p = atomicAdd(&g_ptmp[dst[e]], 1);
        g_csrc[p] = src[e];
    }
}

// ---------------- GEMM: g_FT = x @ W + b  (packed f32x2 inner loop) ----------------
// W layout [H, D, 64]; output col c maps to (h = c/64, k = c%64). OUT = H*64.
// 256 threads, 128-row x OUT-col block tile, K-step 32.
// Thread grid 16(tx, cols) x 16(ty, rows); each thread: 8 rows x CPT cols,
// cols processed as f32x2 pairs (CPT/2 pairs).
// XSRC == 0: read Xparam (harness input). XSRC == 1: read g_X (device global).
template <int D, int OUT, int XSRC>
__global__ void __launch_bounds__(256) k_gemm(const float* __restrict__ Xparam,
                                              const float* __restrict__ W,
                                              const float* __restrict__ B) {
    constexpr int CPT = OUT / 16;      // cols per thread (8 for OUT=128, 4 for 64)
    constexpr int NP  = CPT / 2;       // f32x2 pairs per thread
    __shared__ float Xs[128][33];
    __shared__ float Ws[32][OUT];
    const float* __restrict__ Xp = XSRC ? (const float*)g_X : Xparam;

    int tid = threadIdx.x;
    int tx = tid & 15, ty = tid >> 4;
    int rowBase = blockIdx.x * 128;

    unsigned long long acc[8][NP];
    #pragma unroll
    for (int m = 0; m < 8; m++)
        #pragma unroll
        for (int p = 0; p < NP; p++) acc[m][p] = 0ull;

    for (int k0 = 0; k0 < D; k0 += 32) {
        #pragma unroll 4
        for (int i = tid; i < 128 * 32; i += 256) {
            int r = i >> 5, c = i & 31;
            int gr = rowBase + r;
            Xs[r][c] = (gr < NN) ? Xp[gr * D + k0 + c] : 0.f;
        }
        #pragma unroll 4
        for (int i = tid; i < 32 * OUT; i += 256) {
            int r = i / OUT, c = i % OUT;
            Ws[r][c] = W[(c >> 6) * (D * 64) + (k0 + r) * 64 + (c & 63)];
        }
        __syncthreads();
        #pragma unroll
        for (int kk = 0; kk < 32; kk++) {
            unsigned long long xx[8];
            #pragma unroll
            for (int m = 0; m < 8; m++) xx[m] = pack2(Xs[ty * 8 + m][kk]);
            #pragma unroll
            for (int p = 0; p < NP; p++) {
                unsigned long long wv =
                    *(const unsigned long long*)&Ws[kk][tx * CPT + 2 * p];
                #pragma unroll
                for (int m = 0; m < 8; m++) acc[m][p] = fma2(xx[m], wv, acc[m][p]);
            }
        }
        __syncthreads();
    }
    #pragma unroll
    for (int m = 0; m < 8; m++) {
        int gr = rowBase + ty * 8 + m;
        if (gr < NN) {
            #pragma unroll
            for (int p = 0; p < NP; p++) {
                int c = tx * CPT + 2 * p;
                uint2 u = *(uint2*)&acc[m][p];
                g_FT[gr * OUT + c]     = __uint_as_float(u.x) + B[c];
                g_FT[gr * OUT + c + 1] = __uint_as_float(u.y) + B[c + 1];
            }
        }
    }
}

// ---------------- attention coefficients: a1/a2 per (node, head) ----------------
template <int H>
__global__ void k_attn(const float* __restrict__ al, const float* __restrict__ bl,
                       const float* __restrict__ ar, const float* __restrict__ br) {
    int gw = (blockIdx.x * blockDim.x + threadIdx.x) >> 5;  // node
    int lane = threadIdx.x & 31;
    if (gw >= NN) return;
    #pragma unroll
    for (int h = 0; h < H; h++) {
        const float* f = g_FT + gw * (H * 64) + h * 64;
        float v0 = f[lane], v1 = f[lane + 32];
        float s1 = v0 * al[h * 64 + lane] + v1 * al[h * 64 + lane + 32];
        float s2 = v0 * ar[h * 64 + lane] + v1 * ar[h * 64 + lane + 32];
        #pragma unroll
        for (int o = 16; o; o >>= 1) {
            s1 += __shfl_xor_sync(0xffffffffu, s1, o);
            s2 += __shfl_xor_sync(0xffffffffu, s2, o);
        }
        if (lane == 0) {
            g_A1[gw * H + h] = s1 + bl[h];
            g_A2[gw * H + h] = s2 + br[h];
        }
    }
}

// ---------------- edge softmax + aggregation + elu ----------------
// one warp per (node, head); normalization post-hoc (softmax linear in numerator).
template <int H, bool EXT>
__global__ void k_edge(float* __restrict__ outp) {
    int gw = (blockIdx.x * blockDim.x + threadIdx.x) >> 5;
    int lane = threadIdx.x & 31;
    if (gw >= NN * H) return;
    int n = gw / H, h = gw % H;
    int s0 = g_rowptr[n], s1 = g_rowptr[n + 1];
    float* o = (EXT ? outp : (float*)g_X) + n * (H * 64) + h * 64;
    if (s0 == s1) { o[lane] = 0.f; o[lane + 32] = 0.f; return; }

    float a1 = g_A1[n * H + h];

    // pass 1: segment max
    float m = -INFINITY;
    for (int i = s0 + lane; i < s1; i += 32) {
        float s = a1 + g_A2[g_csrc[i] * H + h];
        s = s > 0.f ? s : 0.01f * s;           // leaky_relu(0.01)
        m = fmaxf(m, s);
    }
    #pragma unroll
    for (int o2 = 16; o2; o2 >>= 1) m = fmaxf(m, __shfl_xor_sync(0xffffffffu, m, o2));

    // pass 2: fused exp / denom / weighted gather-accumulate
    float acc0 = 0.f, acc1 = 0.f, den = 0.f;
    for (int base = s0; base < s1; base += 32) {
        int i = base + lane;
        float e = 0.f; int si = 0;
        if (i < s1) {
            si = g_csrc[i];
            float s = a1 + g_A2[si * H + h];
            s = s > 0.f ? s : 0.01f * s;
            e = __expf(s - m);
        }
        den += e;
        int cnt = min(32, s1 - base);
        for (int j = 0; j < cnt; j++) {
            float ej = __shfl_sync(0xffffffffu, e, j);
            int   sj = __shfl_sync(0xffffffffu, si, j);
            const float* f = g_FT + sj * (H * 64) + h * 64;
            acc0 += ej * f[lane];
            acc1 += ej * f[lane + 32];
        }
    }
    #pragma unroll
    for (int o2 = 16; o2; o2 >>= 1) den += __shfl_xor_sync(0xffffffffu, den, o2);

    float r0 = acc0 / den, r1 = acc1 / den;
    r0 = r0 > 0.f ? r0 : (__expf(r0) - 1.f);   // elu
    r1 = r1 > 0.f ? r1 : (__expf(r1) - 1.f);
    o[lane] = r0;
    o[lane + 32] = r1;
}

// ---------------- launch ----------------
extern "C" void kernel_launch(void* const* d_in, const int* in_sizes, int n_in,
                              void* d_out, int out_size) {
    const float* features = (const float*)d_in[0];
    const int*   src = (const int*)d_in[1];
    const int*   dst = (const int*)d_in[2];
    const float* W0  = (const float*)d_in[3];
    const float* b0  = (const float*)d_in[4];
    const float* al0 = (const float*)d_in[5];
    const float* bl0 = (const float*)d_in[6];
    const float* ar0 = (const float*)d_in[7];
    const float* br0 = (const float*)d_in[8];
    const float* W1  = (const float*)d_in[9];
    const float* b1  = (const float*)d_in[10];
    const float* al1 = (const float*)d_in[11];
    const float* bl1 = (const float*)d_in[12];
    const float* ar1 = (const float*)d_in[13];
    const float* br1 = (const float*)d_in[14];
    const float* Wf  = (const float*)d_in[15];
    const float* bf  = (const float*)d_in[16];
    const float* alf = (const float*)d_in[17];
    const float* blf = (const float*)d_in[18];
    const float* arf = (const float*)d_in[19];
    const float* brf = (const float*)d_in[20];
    float* out = (float*)d_out;

    // CSR build (graph shared by all three layers)
    k_zero_deg<<<(NN + 255) / 256, 256>>>();
    k_count<<<(NE + 255) / 256, 256>>>(dst);
    k_scan<<<1, 1024>>>();
    k_scatter<<<(NE + 255) / 256, 256>>>(src, dst);

    const int gemm_blocks = (NN + 127) / 128;
    const int attn_blocks = (NN + 7) / 8;              // warp per node, 8 warps/block
    const int edge_blocks_h2 = (NN * 2 + 7) / 8;       // warp per (node,head)
    const int edge_blocks_h1 = (NN + 7) / 8;

    // ---- layer 0: IN=256 -> [N, 128] ----
    k_gemm<256, 128, 0><<<gemm_blocks, 256>>>(features, W0, b0);
    k_attn<2><<<attn_blocks, 256>>>(al0, bl0, ar0, br0);
    k_edge<2, false><<<edge_blocks_h2, 256>>>(nullptr);

    // ---- layer 1: 128 -> [N, 128] ----
    k_gemm<128, 128, 1><<<gemm_blocks, 256>>>(nullptr, W1, b1);
    k_attn<2><<<attn_blocks, 256>>>(al1, bl1, ar1, br1);
    k_edge<2, false><<<edge_blocks_h2, 256>>>(nullptr);

    // ---- final layer: 128 -> [N, 64] (H=1) ----
    k_gemm<128, 64, 1><<<gemm_blocks, 256>>>(nullptr, Wf, bf);
    k_attn<1><<<attn_blocks, 256>>>(alf, blf, arf, brf);
    k_edge<1, true><<<edge_blocks_h1, 256>>>(out);
}

// round 8
// speedup vs baseline: 1.2981x; 1.2981x over previous
#include <cuda_runtime.h>
#include <cuda_bf16.h>
#include <math.h>
#include <stdint.h>

// Problem constants (fixed by the dataset)
#define NN 50000
#define NE 800000

// ---------------- device scratch (no allocation allowed) ----------------
__device__ float g_FT[NN * 128];   // per-layer transformed features [N, H*64]
__device__ float g_X[NN * 128];    // layer activations ping buffer  [N, H*64]
__device__ float g_A1[NN * 2];     // dst-side attention logits [N, H]
__device__ float g_A2[NN * 2];     // src-side attention logits [N, H]
__device__ int   g_deg[NN];
__device__ int   g_rowptr[NN + 1];
__device__ int   g_ptmp[NN];
__device__ int   g_csrc[NE];       // CSR (by dst) storing src node ids
// bf16 hi/lo weight images, [n][K] row-major (n = output column)
__device__ unsigned short g_Bh0[128 * 256], g_Bl0[128 * 256];
__device__ unsigned short g_Bh1[128 * 128], g_Bl1[128 * 128];
__device__ unsigned short g_Bhf[64 * 128],  g_Blf[64 * 128];

// ---------------- mma.sync helpers (portable sm_80+ HMMA path) ----------------
__device__ __forceinline__ void mma_bf16(float* d, const uint32_t* a, const uint32_t* b) {
    asm volatile("mma.sync.aligned.m16n8k16.row.col.f32.bf16.bf16.f32 "
                 "{%0,%1,%2,%3}, {%4,%5,%6,%7}, {%8,%9}, {%0,%1,%2,%3};"
                 : "+f"(d[0]), "+f"(d[1]), "+f"(d[2]), "+f"(d[3])
                 : "r"(a[0]), "r"(a[1]), "r"(a[2]), "r"(a[3]), "r"(b[0]), "r"(b[1]));
}
// split float2 -> packed bf16x2 hi + lo (lo = x - hi, exactly representable path)
__device__ __forceinline__ void cvt_split(float2 x, uint32_t& h, uint32_t& l) {
    asm("cvt.rn.bf16x2.f32 %0, %1, %2;" : "=r"(h) : "f"(x.y), "f"(x.x));
    float h0 = __uint_as_float(h << 16);
    float h1 = __uint_as_float(h & 0xFFFF0000u);
    float l0 = x.x - h0, l1 = x.y - h1;
    asm("cvt.rn.bf16x2.f32 %0, %1, %2;" : "=r"(l) : "f"(l1), "f"(l0));
}

// ---------------- CSR build ----------------
__global__ void k_zero_deg() {
    int i = blockIdx.x * blockDim.x + threadIdx.x;
    if (i < NN) g_deg[i] = 0;
}

__global__ void k_count(const int* __restrict__ dst) {
    int e = blockIdx.x * blockDim.x + threadIdx.x;
    if (e < NE) atomicAdd(&g_deg[dst[e]], 1);
}

// single-block exclusive scan, 16 elements per thread
__global__ void k_scan() {
    __shared__ int warp_tot[32];
    __shared__ int warp_pref[32];
    __shared__ int s_total;
    __shared__ int s_carry;
    const int VPT = 16;
    int tid = threadIdx.x, lane = tid & 31, wid = tid >> 5;
    if (tid == 0) { s_carry = 0; g_rowptr[0] = 0; }
    __syncthreads();
    for (int base = 0; base < NN; base += 1024 * VPT) {
        int i0 = base + tid * VPT;
        int v[VPT];
        int sum = 0;
        #pragma unroll
        for (int j = 0; j < VPT; j++) {
            v[j] = (i0 + j < NN) ? g_deg[i0 + j] : 0;
            sum += v[j];
        }
        int x = sum;
        #pragma unroll
        for (int off = 1; off < 32; off <<= 1) {
            int t = __shfl_up_sync(0xffffffffu, x, off);
            if (lane >= off) x += t;
        }
        if (lane == 31) warp_tot[wid] = x;
        __syncthreads();
        if (wid == 0) {
            int w = warp_tot[lane];
            int y = w;
            #pragma unroll
            for (int off = 1; off < 32; off <<= 1) {
                int t = __shfl_up_sync(0xffffffffu, y, off);
                if (lane >= off) y += t;
            }
            warp_pref[lane] = y - w;
            if (lane == 31) s_total = y;
        }
        __syncthreads();
        int run = s_carry + warp_pref[wid] + (x - sum);
        #pragma unroll
        for (int j = 0; j < VPT; j++) {
            if (i0 + j < NN) {
                g_ptmp[i0 + j] = run;
                run += v[j];
                g_rowptr[i0 + j + 1] = run;
            }
        }
        __syncthreads();
        if (tid == 0) s_carry += s_total;
        __syncthreads();
    }
}

__global__ void k_scatter(const int* __restrict__ src, const int* __restrict__ dst) {
    int e = blockIdx.x * blockDim.x + threadIdx.x;
    if (e < NE) {
        int p = atomicAdd(&g_ptmp[dst[e]], 1);
        g_csrc[p] = src[e];
    }
}

// ---------------- W pre-conversion: fp32 -> bf16 hi/lo, [n][D] row-major ----------
// W layout [H, D, 64]; output col n maps to (h = n/64, k = n%64).
template <int D, int OUT, int L>
__global__ void k_wconv(const float* __restrict__ W) {
    unsigned short* Bh = (L == 0) ? g_Bh0 : (L == 1) ? g_Bh1 : g_Bhf;
    unsigned short* Bl = (L == 0) ? g_Bl0 : (L == 1) ? g_Bl1 : g_Blf;
    int idx = blockIdx.x * blockDim.x + threadIdx.x;
    if (idx >= OUT * D) return;
    int n = idx / D, k = idx % D;
    float x = W[(n >> 6) * (D * 64) + k * 64 + (n & 63)];
    __nv_bfloat16 h = __float2bfloat16(x);
    __nv_bfloat16 l = __float2bfloat16(x - __bfloat162float(h));
    Bh[n * D + k] = *(unsigned short*)&h;
    Bl[n * D + k] = *(unsigned short*)&l;
}

// ---------------- GEMM via mma.sync (bf16-split, fp32 accum) ----------------
// CTA: 256 threads = 8 warps, 64-row tile. OUT=128: warp = 32r x 32c (WM=2).
// OUT=64: warp = 16r x 32c (WM=1). No smem, no syncs; A read as float2 from
// gmem and split in registers; B from pre-converted L2-resident images.
template <int D, int OUT, int XSRC, int L>
__global__ void __launch_bounds__(256) k_gemm_mma(const float* __restrict__ Xparam,
                                                  const float* __restrict__ Bias) {
    constexpr int WN = 4;                 // n8 tiles per warp (32 cols)
    constexpr int WC = OUT / 32;          // warps along cols
    constexpr int WR = 8 / WC;            // warps along rows
    constexpr int WM = 64 / (WR * 16);    // m16 tiles per warp

    const float* __restrict__ Xp = XSRC ? (const float*)g_X : Xparam;
    const unsigned short* __restrict__ Bh = (L == 0) ? g_Bh0 : (L == 1) ? g_Bh1 : g_Bhf;
    const unsigned short* __restrict__ Bl = (L == 0) ? g_Bl0 : (L == 1) ? g_Bl1 : g_Blf;

    int tid = threadIdx.x, wid = tid >> 5, lane = tid & 31;
    int wr = wid / WC, wc = wid % WC;
    int rowBase = blockIdx.x * 64 + wr * (WM * 16);
    int colBase = wc * 32;
    int tq = lane >> 2, tr = lane & 3;

    float acc[WM][WN][4];
    #pragma unroll
    for (int m = 0; m < WM; m++)
        #pragma unroll
        for (int n = 0; n < WN; n++)
            #pragma unroll
            for (int i = 0; i < 4; i++) acc[m][n][i] = 0.f;

    for (int k0 = 0; k0 < D; k0 += 16) {
        // B fragments (col n = tq; rows k0+tr*2, +1, +8, +9)
        uint32_t bh[WN][2], bl[WN][2];
        #pragma unroll
        for (int n = 0; n < WN; n++) {
            int off = (colBase + n * 8 + tq) * D + k0 + tr * 2;
            bh[n][0] = *(const uint32_t*)(Bh + off);
            bh[n][1] = *(const uint32_t*)(Bh + off + 8);
            bl[n][0] = *(const uint32_t*)(Bl + off);
            bl[n][1] = *(const uint32_t*)(Bl + off + 8);
        }
        #pragma unroll
        for (int m = 0; m < WM; m++) {
            int r0 = rowBase + m * 16 + tq;
            int r1 = r0 + 8;
            const float* p0 = Xp + r0 * D + k0 + tr * 2;
            const float* p1 = Xp + r1 * D + k0 + tr * 2;
            float2 z = make_float2(0.f, 0.f);
            float2 x00 = (r0 < NN) ? *(const float2*)(p0)     : z;
            float2 x01 = (r0 < NN) ? *(const float2*)(p0 + 8) : z;
            float2 x10 = (r1 < NN) ? *(const float2*)(p1)     : z;
            float2 x11 = (r1 < NN) ? *(const float2*)(p1 + 8) : z;
            uint32_t ah[4], al[4];
            cvt_split(x00, ah[0], al[0]);
            cvt_split(x10, ah[1], al[1]);
            cvt_split(x01, ah[2], al[2]);
            cvt_split(x11, ah[3], al[3]);
            #pragma unroll
            for (int n = 0; n < WN; n++) {
                mma_bf16(acc[m][n], ah, bh[n]);
                mma_bf16(acc[m][n], ah, bl[n]);
                mma_bf16(acc[m][n], al, bh[n]);
            }
        }
    }

    // epilogue: d-frag rows = tq (+8), cols = tr*2 + {0,1}
    #pragma unroll
    for (int m = 0; m < WM; m++) {
        int r0 = rowBase + m * 16 + tq;
        int r1 = r0 + 8;
        #pragma unroll
        for (int n = 0; n < WN; n++) {
            int c = colBase + n * 8 + tr * 2;
            float bA = Bias[c], bB = Bias[c + 1];
            if (r0 < NN) {
                float2 v = make_float2(acc[m][n][0] + bA, acc[m][n][1] + bB);
                *(float2*)(g_FT + r0 * OUT + c) = v;
            }
            if (r1 < NN) {
                float2 v = make_float2(acc[m][n][2] + bA, acc[m][n][3] + bB);
                *(float2*)(g_FT + r1 * OUT + c) = v;
            }
        }
    }
}

// ---------------- attention coefficients: a1/a2 per (node, head) ----------------
template <int H>
__global__ void k_attn(const float* __restrict__ al, const float* __restrict__ bl,
                       const float* __restrict__ ar, const float* __restrict__ br) {
    int gw = (blockIdx.x * blockDim.x + threadIdx.x) >> 5;  // node
    int lane = threadIdx.x & 31;
    if (gw >= NN) return;
    #pragma unroll
    for (int h = 0; h < H; h++) {
        const float* f = g_FT + gw * (H * 64) + h * 64;
        float v0 = f[lane], v1 = f[lane + 32];
        float s1 = v0 * al[h * 64 + lane] + v1 * al[h * 64 + lane + 32];
        float s2 = v0 * ar[h * 64 + lane] + v1 * ar[h * 64 + lane + 32];
        #pragma unroll
        for (int o = 16; o; o >>= 1) {
            s1 += __shfl_xor_sync(0xffffffffu, s1, o);
            s2 += __shfl_xor_sync(0xffffffffu, s2, o);
        }
        if (lane == 0) {
            g_A1[gw * H + h] = s1 + bl[h];
            g_A2[gw * H + h] = s2 + br[h];
        }
    }
}

// ---------------- edge softmax + aggregation + elu ----------------
template <int H, bool EXT>
__global__ void k_edge(float* __restrict__ outp) {
    int gw = (blockIdx.x * blockDim.x + threadIdx.x) >> 5;
    int lane = threadIdx.x & 31;
    if (gw >= NN * H) return;
    int n = gw / H, h = gw % H;
    int s0 = g_rowptr[n], s1 = g_rowptr[n + 1];
    float* o = (EXT ? outp : (float*)g_X) + n * (H * 64) + h * 64;
    if (s0 == s1) { o[lane] = 0.f; o[lane + 32] = 0.f; return; }

    float a1 = g_A1[n * H + h];

    float m = -INFINITY;
    for (int i = s0 + lane; i < s1; i += 32) {
        float s = a1 + g_A2[g_csrc[i] * H + h];
        s = s > 0.f ? s : 0.01f * s;           // leaky_relu(0.01)
        m = fmaxf(m, s);
    }
    #pragma unroll
    for (int o2 = 16; o2; o2 >>= 1) m = fmaxf(m, __shfl_xor_sync(0xffffffffu, m, o2));

    float acc0 = 0.f, acc1 = 0.f, den = 0.f;
    for (int base = s0; base < s1; base += 32) {
        int i = base + lane;
        float e = 0.f; int si = 0;
        if (i < s1) {
            si = g_csrc[i];
            float s = a1 + g_A2[si * H + h];
            s = s > 0.f ? s : 0.01f * s;
            e = __expf(s - m);
        }
        den += e;
        int cnt = min(32, s1 - base);
        for (int j = 0; j < cnt; j++) {
            float ej = __shfl_sync(0xffffffffu, e, j);
            int   sj = __shfl_sync(0xffffffffu, si, j);
            const float* f = g_FT + sj * (H * 64) + h * 64;
            acc0 += ej * f[lane];
            acc1 += ej * f[lane + 32];
        }
    }
    #pragma unroll
    for (int o2 = 16; o2; o2 >>= 1) den += __shfl_xor_sync(0xffffffffu, den, o2);

    float r0 = acc0 / den, r1 = acc1 / den;
    r0 = r0 > 0.f ? r0 : (__expf(r0) - 1.f);   // elu
    r1 = r1 > 0.f ? r1 : (__expf(r1) - 1.f);
    o[lane] = r0;
    o[lane + 32] = r1;
}

// ---------------- launch ----------------
extern "C" void kernel_launch(void* const* d_in, const int* in_sizes, int n_in,
                              void* d_out, int out_size) {
    const float* features = (const float*)d_in[0];
    const int*   src = (const int*)d_in[1];
    const int*   dst = (const int*)d_in[2];
    const float* W0  = (const float*)d_in[3];
    const float* b0  = (const float*)d_in[4];
    const float* al0 = (const float*)d_in[5];
    const float* bl0 = (const float*)d_in[6];
    const float* ar0 = (const float*)d_in[7];
    const float* br0 = (const float*)d_in[8];
    const float* W1  = (const float*)d_in[9];
    const float* b1  = (const float*)d_in[10];
    const float* al1 = (const float*)d_in[11];
    const float* bl1 = (const float*)d_in[12];
    const float* ar1 = (const float*)d_in[13];
    const float* br1 = (const float*)d_in[14];
    const float* Wf  = (const float*)d_in[15];
    const float* bf  = (const float*)d_in[16];
    const float* alf = (const float*)d_in[17];
    const float* blf = (const float*)d_in[18];
    const float* arf = (const float*)d_in[19];
    const float* brf = (const float*)d_in[20];
    float* out = (float*)d_out;

    // weight pre-conversion (tiny)
    k_wconv<256, 128, 0><<<(128 * 256 + 255) / 256, 256>>>(W0);
    k_wconv<128, 128, 1><<<(128 * 128 + 255) / 256, 256>>>(W1);
    k_wconv<128, 64, 2><<<(64 * 128 + 255) / 256, 256>>>(Wf);

    // CSR build (graph shared by all three layers)
    k_zero_deg<<<(NN + 255) / 256, 256>>>();
    k_count<<<(NE + 255) / 256, 256>>>(dst);
    k_scan<<<1, 1024>>>();
    k_scatter<<<(NE + 255) / 256, 256>>>(src, dst);

    const int gemm_blocks = (NN + 63) / 64;            // 782
    const int attn_blocks = (NN + 7) / 8;
    const int edge_blocks_h2 = (NN * 2 + 7) / 8;
    const int edge_blocks_h1 = (NN + 7) / 8;

    // ---- layer 0: IN=256 -> [N, 128] ----
    k_gemm_mma<256, 128, 0, 0><<<gemm_blocks, 256>>>(features, b0);
    k_attn<2><<<attn_blocks, 256>>>(al0, bl0, ar0, br0);
    k_edge<2, false><<<edge_blocks_h2, 256>>>(nullptr);

    // ---- layer 1: 128 -> [N, 128] ----
    k_gemm_mma<128, 128, 1, 1><<<gemm_blocks, 256>>>(nullptr, b1);
    k_attn<2><<<attn_blocks, 256>>>(al1, bl1, ar1, br1);
    k_edge<2, false><<<edge_blocks_h2, 256>>>(nullptr);

    // ---- final layer: 128 -> [N, 64] (H=1) ----
    k_gemm_mma<128, 64, 1, 2><<<gemm_blocks, 256>>>(nullptr, bf);
    k_attn<1><<<attn_blocks, 256>>>(alf, blf, arf, brf);
    k_edge<1, true><<<edge_blocks_h1, 256>>>(out);
}

// round 11
// speedup vs baseline: 1.3733x; 1.0579x over previous
#include <cuda_runtime.h>
#include <cuda_bf16.h>
#include <math.h>
#include <stdint.h>

// Problem constants (fixed by the dataset)
#define NN 50000
#define NE 800000

// ---------------- device scratch (no allocation allowed) ----------------
__device__ float g_FT[NN * 128];   // per-layer transformed features [N, H*64]
__device__ uint2 g_Xs[NN * 128];   // pre-split activations: (hi,lo) bf16x2 per k-pair
                                   // layer0: stride 128 pairs; layers1/f: stride 64
__device__ float g_A1[NN * 2];     // dst-side attention logits [N, H]
__device__ float g_A2[NN * 2];     // src-side attention logits [N, H]
__device__ int   g_deg[NN];
__device__ int   g_rowptr[NN + 1];
__device__ int   g_ptmp[NN];
__device__ int   g_csrc[NE];       // CSR (by dst) storing src node ids
// pre-split weights: (hi,lo) bf16x2 per (outcol, k-pair), [n][D/2]
__device__ uint2 g_Bs0[128 * 128];
__device__ uint2 g_Bs1[128 * 64];
__device__ uint2 g_Bsf[64 * 64];

// ---------------- mma.sync helpers (portable sm_80+ HMMA path) ----------------
__device__ __forceinline__ void mma_bf16(float* d, const uint32_t* a, const uint32_t* b) {
    asm volatile("mma.sync.aligned.m16n8k16.row.col.f32.bf16.bf16.f32 "
                 "{%0,%1,%2,%3}, {%4,%5,%6,%7}, {%8,%9}, {%0,%1,%2,%3};"
                 : "+f"(d[0]), "+f"(d[1]), "+f"(d[2]), "+f"(d[3])
                 : "r"(a[0]), "r"(a[1]), "r"(a[2]), "r"(a[3]), "r"(b[0]), "r"(b[1]));
}
// split float2 -> packed bf16x2 hi + lo (x.x in low half, x.y in high half)
__device__ __forceinline__ void cvt_split(float2 x, uint32_t& h, uint32_t& l) {
    asm("cvt.rn.bf16x2.f32 %0, %1, %2;" : "=r"(h) : "f"(x.y), "f"(x.x));
    float h0 = __uint_as_float(h << 16);
    float h1 = __uint_as_float(h & 0xFFFF0000u);
    float l0 = x.x - h0, l1 = x.y - h1;
    asm("cvt.rn.bf16x2.f32 %0, %1, %2;" : "=r"(l) : "f"(l1), "f"(l0));
}

// ---------------- CSR build ----------------
__global__ void k_zero_deg() {
    int i = blockIdx.x * blockDim.x + threadIdx.x;
    if (i < NN) g_deg[i] = 0;
}

__global__ void k_count(const int* __restrict__ dst) {
    int e = blockIdx.x * blockDim.x + threadIdx.x;
    if (e < NE) atomicAdd(&g_deg[dst[e]], 1);
}

// single-block exclusive scan, 16 elements per thread
__global__ void k_scan() {
    __shared__ int warp_tot[32];
    __shared__ int warp_pref[32];
    __shared__ int s_total;
    __shared__ int s_carry;
    const int VPT = 16;
    int tid = threadIdx.x, lane = tid & 31, wid = tid >> 5;
    if (tid == 0) { s_carry = 0; g_rowptr[0] = 0; }
    __syncthreads();
    for (int base = 0; base < NN; base += 1024 * VPT) {
        int i0 = base + tid * VPT;
        int v[VPT];
        int sum = 0;
        #pragma unroll
        for (int j = 0; j < VPT; j++) {
            v[j] = (i0 + j < NN) ? g_deg[i0 + j] : 0;
            sum += v[j];
        }
        int x = sum;
        #pragma unroll
        for (int off = 1; off < 32; off <<= 1) {
            int t = __shfl_up_sync(0xffffffffu, x, off);
            if (lane >= off) x += t;
        }
        if (lane == 31) warp_tot[wid] = x;
        __syncthreads();
        if (wid == 0) {
            int w = warp_tot[lane];
            int y = w;
            #pragma unroll
            for (int off = 1; off < 32; off <<= 1) {
                int t = __shfl_up_sync(0xffffffffu, y, off);
                if (lane >= off) y += t;
            }
            warp_pref[lane] = y - w;
            if (lane == 31) s_total = y;
        }
        __syncthreads();
        int run = s_carry + warp_pref[wid] + (x - sum);
        #pragma unroll
        for (int j = 0; j < VPT; j++) {
            if (i0 + j < NN) {
                g_ptmp[i0 + j] = run;
                run += v[j];
                g_rowptr[i0 + j + 1] = run;
            }
        }
        __syncthreads();
        if (tid == 0) s_carry += s_total;
        __syncthreads();
    }
}

__global__ void k_scatter(const int* __restrict__ src, const int* __restrict__ dst) {
    int e = blockIdx.x * blockDim.x + threadIdx.x;
    if (e < NE) {
        int p = atomicAdd(&g_ptmp[dst[e]], 1);
        g_csrc[p] = src[e];
    }
}

// ---------------- feature pre-split (layer 0 input) ----------------
__global__ void k_xconv(const float* __restrict__ X) {
    int idx = blockIdx.x * blockDim.x + threadIdx.x;   // over NN*128 pairs
    if (idx >= NN * 128) return;
    float2 x = *(const float2*)(X + idx * 2);
    uint32_t h, l;
    cvt_split(x, h, l);
    g_Xs[idx] = make_uint2(h, l);
}

// ---------------- W pre-split: fp32 -> (hi,lo) bf16x2, [n][D/2] ----------------
// W layout [H, D, 64]; output col n maps to (h = n/64, k = n%64).
template <int D, int OUT, int L>
__global__ void k_wconv(const float* __restrict__ W) {
    uint2* Bs = (L == 0) ? g_Bs0 : (L == 1) ? g_Bs1 : g_Bsf;
    int idx = blockIdx.x * blockDim.x + threadIdx.x;   // over OUT*(D/2)
    if (idx >= OUT * (D / 2)) return;
    int n = idx / (D / 2), p = idx % (D / 2);
    int k = 2 * p;
    float x0 = W[(n >> 6) * (D * 64) + k * 64 + (n & 63)];
    float x1 = W[(n >> 6) * (D * 64) + (k + 1) * 64 + (n & 63)];
    uint32_t h, l;
    cvt_split(make_float2(x0, x1), h, l);
    Bs[idx] = make_uint2(h, l);
}

// ---------------- GEMM via mma.sync (pre-split bf16, fp32 accum) ----------------
// CTA: 256 threads = 8 warps, 64-row tile. OUT=128: warp = 32r x 32c (WM=2).
// OUT=64: warp = 16r x 32c (WM=1). No smem, no syncs; inner loop is pure
// LDG.64 + HMMA.  acc = Ah@Bh + Ah@Bl + Al@Bh (lo*lo dropped, ~2^-16 rel).
// SP = pairs per activation row in g_Xs.
template <int D, int OUT, int SP, int L>
__global__ void __launch_bounds__(256) k_gemm_mma(const float* __restrict__ Bias) {
    constexpr int WN = 4;                 // n8 tiles per warp (32 cols)
    constexpr int WC = OUT / 32;          // warps along cols
    constexpr int WR = 8 / WC;            // warps along rows
    constexpr int WM = 64 / (WR * 16);    // m16 tiles per warp

    const uint2* __restrict__ Bs = (L == 0) ? g_Bs0 : (L == 1) ? g_Bs1 : g_Bsf;

    int tid = threadIdx.x, wid = tid >> 5, lane = tid & 31;
    int wr = wid / WC, wc = wid % WC;
    int rowBase = blockIdx.x * 64 + wr * (WM * 16);
    int colBase = wc * 32;
    int tq = lane >> 2, tr = lane & 3;

    float acc[WM][WN][4];
    #pragma unroll
    for (int m = 0; m < WM; m++)
        #pragma unroll
        for (int n = 0; n < WN; n++)
            #pragma unroll
            for (int i = 0; i < 4; i++) acc[m][n][i] = 0.f;

    for (int kp0 = 0; kp0 < D / 2; kp0 += 8) {        // 16 k's per step
        // B fragments: col = colBase + n*8 + tq; pairs kp0+tr, kp0+tr+4
        uint32_t bh[WN][2], bl[WN][2];
        #pragma unroll
        for (int n = 0; n < WN; n++) {
            const uint2* bp = Bs + (colBase + n * 8 + tq) * (D / 2) + kp0 + tr;
            uint2 u0 = bp[0], u1 = bp[4];
            bh[n][0] = u0.x; bl[n][0] = u0.y;
            bh[n][1] = u1.x; bl[n][1] = u1.y;
        }
        #pragma unroll
        for (int m = 0; m < WM; m++) {
            int r0 = rowBase + m * 16 + tq;
            int r1 = r0 + 8;
            const uint2* p0 = g_Xs + r0 * SP + kp0 + tr;
            const uint2* p1 = g_Xs + r1 * SP + kp0 + tr;
            uint2 z = make_uint2(0u, 0u);
            uint2 q00 = (r0 < NN) ? p0[0] : z;
            uint2 q01 = (r0 < NN) ? p0[4] : z;
            uint2 q10 = (r1 < NN) ? p1[0] : z;
            uint2 q11 = (r1 < NN) ? p1[4] : z;
            uint32_t ah[4] = {q00.x, q10.x, q01.x, q11.x};
            uint32_t al[4] = {q00.y, q10.y, q01.y, q11.y};
            #pragma unroll
            for (int n = 0; n < WN; n++) {
                mma_bf16(acc[m][n], ah, bh[n]);
                mma_bf16(acc[m][n], ah, bl[n]);
                mma_bf16(acc[m][n], al, bh[n]);
            }
        }
    }

    // epilogue: d-frag rows = tq (+8), cols = tr*2 + {0,1}
    #pragma unroll
    for (int m = 0; m < WM; m++) {
        int r0 = rowBase + m * 16 + tq;
        int r1 = r0 + 8;
        #pragma unroll
        for (int n = 0; n < WN; n++) {
            int c = colBase + n * 8 + tr * 2;
            float bA = Bias[c], bB = Bias[c + 1];
            if (r0 < NN) {
                float2 v = make_float2(acc[m][n][0] + bA, acc[m][n][1] + bB);
                *(float2*)(g_FT + r0 * OUT + c) = v;
            }
            if (r1 < NN) {
                float2 v = make_float2(acc[m][n][2] + bA, acc[m][n][3] + bB);
                *(float2*)(g_FT + r1 * OUT + c) = v;
            }
        }
    }
}

// ---------------- attention coefficients: a1/a2 per (node, head) ----------------
template <int H>
__global__ void k_attn(const float* __restrict__ al, const float* __restrict__ bl,
                       const float* __restrict__ ar, const float* __restrict__ br) {
    int gw = (blockIdx.x * blockDim.x + threadIdx.x) >> 5;  // node
    int lane = threadIdx.x & 31;
    if (gw >= NN) return;
    #pragma unroll
    for (int h = 0; h < H; h++) {
        const float* f = g_FT + gw * (H * 64) + h * 64;
        float v0 = f[lane], v1 = f[lane + 32];
        float s1 = v0 * al[h * 64 + lane] + v1 * al[h * 64 + lane + 32];
        float s2 = v0 * ar[h * 64 + lane] + v1 * ar[h * 64 + lane + 32];
        #pragma unroll
        for (int o = 16; o; o >>= 1) {
            s1 += __shfl_xor_sync(0xffffffffu, s1, o);
            s2 += __shfl_xor_sync(0xffffffffu, s2, o);
        }
        if (lane == 0) {
            g_A1[gw * H + h] = s1 + bl[h];
            g_A2[gw * H + h] = s2 + br[h];
        }
    }
}

// ---------------- edge softmax + aggregation + elu ----------------
// one warp per (node, head); lane handles adjacent cols (2*lane, 2*lane+1).
// EXT == false: writes pre-split bf16 (hi,lo) packs into g_Xs (stride 64 pairs)
// for the next layer's GEMM. EXT == true: writes fp32 to outp.
template <int H, bool EXT>
__global__ void k_edge(float* __restrict__ outp) {
    int gw = (blockIdx.x * blockDim.x + threadIdx.x) >> 5;
    int lane = threadIdx.x & 31;
    if (gw >= NN * H) return;
    int n = gw / H, h = gw % H;
    int s0 = g_rowptr[n], s1 = g_rowptr[n + 1];
    if (s0 == s1) {
        if (EXT) *(float2*)(outp + n * 64 + 2 * lane) = make_float2(0.f, 0.f);
        else     g_Xs[n * 64 + h * 32 + lane] = make_uint2(0u, 0u);
        return;
    }

    float a1 = g_A1[n * H + h];

    // pass 1: segment max
    float m = -INFINITY;
    for (int i = s0 + lane; i < s1; i += 32) {
        float s = a1 + g_A2[g_csrc[i] * H + h];
        s = s > 0.f ? s : 0.01f * s;           // leaky_relu(0.01)
        m = fmaxf(m, s);
    }
    #pragma unroll
    for (int o2 = 16; o2; o2 >>= 1) m = fmaxf(m, __shfl_xor_sync(0xffffffffu, m, o2));

    // pass 2: fused exp / denom / weighted gather-accumulate
    float acc0 = 0.f, acc1 = 0.f, den = 0.f;
    for (int base = s0; base < s1; base += 32) {
        int i = base + lane;
        float e = 0.f; int si = 0;
        if (i < s1) {
            si = g_csrc[i];
            float s = a1 + g_A2[si * H + h];
            s = s > 0.f ? s : 0.01f * s;
            e = __expf(s - m);
        }
        den += e;
        int cnt = min(32, s1 - base);
        for (int j = 0; j < cnt; j++) {
            float ej = __shfl_sync(0xffffffffu, e, j);
            int   sj = __shfl_sync(0xffffffffu, si, j);
            float2 fv = *(const float2*)(g_FT + sj * (H * 64) + h * 64 + 2 * lane);
            acc0 += ej * fv.x;
            acc1 += ej * fv.y;
        }
    }
    #pragma unroll
    for (int o2 = 16; o2; o2 >>= 1) den += __shfl_xor_sync(0xffffffffu, den, o2);

    float r0 = acc0 / den, r1 = acc1 / den;
    r0 = r0 > 0.f ? r0 : (__expf(r0) - 1.f);   // elu
    r1 = r1 > 0.f ? r1 : (__expf(r1) - 1.f);
    if (EXT) {
        *(float2*)(outp + n * 64 + 2 * lane) = make_float2(r0, r1);
    } else {
        uint32_t hp, lp;
        cvt_split(make_float2(r0, r1), hp, lp);
        g_Xs[n * 64 + h * 32 + lane] = make_uint2(hp, lp);
    }
}

// ---------------- launch ----------------
extern "C" void kernel_launch(void* const* d_in, const int* in_sizes, int n_in,
                              void* d_out, int out_size) {
    const float* features = (const float*)d_in[0];
    const int*   src = (const int*)d_in[1];
    const int*   dst = (const int*)d_in[2];
    const float* W0  = (const float*)d_in[3];
    const float* b0  = (const float*)d_in[4];
    const float* al0 = (const float*)d_in[5];
    const float* bl0 = (const float*)d_in[6];
    const float* ar0 = (const float*)d_in[7];
    const float* br0 = (const float*)d_in[8];
    const float* W1  = (const float*)d_in[9];
    const float* b1  = (const float*)d_in[10];
    const float* al1 = (const float*)d_in[11];
    const float* bl1 = (const float*)d_in[12];
    const float* ar1 = (const float*)d_in[13];
    const float* br1 = (const float*)d_in[14];
    const float* Wf  = (const float*)d_in[15];
    const float* bf  = (const float*)d_in[16];
    const float* alf = (const float*)d_in[17];
    const float* blf = (const float*)d_in[18];
    const float* arf = (const float*)d_in[19];
    const float* brf = (const float*)d_in[20];
    float* out = (float*)d_out;

    // pre-split conversions (weights tiny; features ~13 us bandwidth-bound)
    k_wconv<256, 128, 0><<<(128 * 128 + 255) / 256, 256>>>(W0);
    k_wconv<128, 128, 1><<<(128 * 64 + 255) / 256, 256>>>(W1);
    k_wconv<128, 64, 2><<<(64 * 64 + 255) / 256, 256>>>(Wf);
    k_xconv<<<(NN * 128 + 255) / 256, 256>>>(features);

    // CSR build (graph shared by all three layers)
    k_zero_deg<<<(NN + 255) / 256, 256>>>();
    k_count<<<(NE + 255) / 256, 256>>>(dst);
    k_scan<<<1, 1024>>>();
    k_scatter<<<(NE + 255) / 256, 256>>>(src, dst);

    const int gemm_blocks = (NN + 63) / 64;            // 782
    const int attn_blocks = (NN + 7) / 8;
    const int edge_blocks_h2 = (NN * 2 + 7) / 8;
    const int edge_blocks_h1 = (NN + 7) / 8;

    // ---- layer 0: IN=256 -> [N, 128] ----
    k_gemm_mma<256, 128, 128, 0><<<gemm_blocks, 256>>>(b0);
    k_attn<2><<<attn_blocks, 256>>>(al0, bl0, ar0, br0);
    k_edge<2, false><<<edge_blocks_h2, 256>>>(nullptr);

    // ---- layer 1: 128 -> [N, 128] ----
    k_gemm_mma<128, 128, 64, 1><<<gemm_blocks, 256>>>(b1);
    k_attn<2><<<attn_blocks, 256>>>(al1, bl1, ar1, br1);
    k_edge<2, false><<<edge_blocks_h2, 256>>>(nullptr);

    // ---- final layer: 128 -> [N, 64] (H=1) ----
    k_gemm_mma<128, 64, 64, 2><<<gemm_blocks, 256>>>(bf);
    k_attn<1><<<attn_blocks, 256>>>(alf, blf, arf, brf);
    k_edge<1, true><<<edge_blocks_h1, 256>>>(out);
}

// round 12
// speedup vs baseline: 1.4609x; 1.0638x over previous
#include <cuda_runtime.h>
#include <cuda_bf16.h>
#include <math.h>
#include <stdint.h>

// Problem constants (fixed by the dataset)
#define NN 50000
#define NE 800000

// ---------------- device scratch (no allocation allowed) ----------------
__device__ float g_FT[NN * 128];   // per-layer transformed features [N, H*64]
__device__ uint2 g_Xs[NN * 128];   // pre-split activations: (hi,lo) bf16x2 per k-pair
__device__ float g_A1[NN * 2];     // dst-side attention logits [N, H]
__device__ float g_A2[NN * 2];     // src-side attention logits [N, H]
__device__ int   g_deg[NN];
__device__ int   g_rowptr[NN + 1];
__device__ int   g_ptmp[NN];
__device__ int   g_csrc[NE];       // CSR (by dst) storing src node ids
// pre-split weights: (hi,lo) bf16x2 per (outcol, k-pair), [n][D/2]
__device__ uint2 g_Bs0[128 * 128];
__device__ uint2 g_Bs1[128 * 64];
__device__ uint2 g_Bsf[64 * 64];

// ---------------- mma.sync helpers (portable sm_80+ HMMA path) ----------------
__device__ __forceinline__ void mma_bf16(float* d, const uint32_t* a, const uint32_t* b) {
    asm volatile("mma.sync.aligned.m16n8k16.row.col.f32.bf16.bf16.f32 "
                 "{%0,%1,%2,%3}, {%4,%5,%6,%7}, {%8,%9}, {%0,%1,%2,%3};"
                 : "+f"(d[0]), "+f"(d[1]), "+f"(d[2]), "+f"(d[3])
                 : "r"(a[0]), "r"(a[1]), "r"(a[2]), "r"(a[3]), "r"(b[0]), "r"(b[1]));
}
// split float2 -> packed bf16x2 hi + lo (x.x in low half, x.y in high half)
__device__ __forceinline__ void cvt_split(float2 x, uint32_t& h, uint32_t& l) {
    asm("cvt.rn.bf16x2.f32 %0, %1, %2;" : "=r"(h) : "f"(x.y), "f"(x.x));
    float h0 = __uint_as_float(h << 16);
    float h1 = __uint_as_float(h & 0xFFFF0000u);
    float l0 = x.x - h0, l1 = x.y - h1;
    asm("cvt.rn.bf16x2.f32 %0, %1, %2;" : "=r"(l) : "f"(l1), "f"(l0));
}

// ---------------- CSR build ----------------
__global__ void k_zero_deg() {
    int i = blockIdx.x * blockDim.x + threadIdx.x;
    if (i < NN) g_deg[i] = 0;
}

__global__ void k_count(const int* __restrict__ dst) {
    int e = blockIdx.x * blockDim.x + threadIdx.x;
    if (e < NE) atomicAdd(&g_deg[dst[e]], 1);
}

// single-block exclusive scan, 16 elements per thread
__global__ void k_scan() {
    __shared__ int warp_tot[32];
    __shared__ int warp_pref[32];
    __shared__ int s_total;
    __shared__ int s_carry;
    const int VPT = 16;
    int tid = threadIdx.x, lane = tid & 31, wid = tid >> 5;
    if (tid == 0) { s_carry = 0; g_rowptr[0] = 0; }
    __syncthreads();
    for (int base = 0; base < NN; base += 1024 * VPT) {
        int i0 = base + tid * VPT;
        int v[VPT];
        int sum = 0;
        #pragma unroll
        for (int j = 0; j < VPT; j++) {
            v[j] = (i0 + j < NN) ? g_deg[i0 + j] : 0;
            sum += v[j];
        }
        int x = sum;
        #pragma unroll
        for (int off = 1; off < 32; off <<= 1) {
            int t = __shfl_up_sync(0xffffffffu, x, off);
            if (lane >= off) x += t;
        }
        if (lane == 31) warp_tot[wid] = x;
        __syncthreads();
        if (wid == 0) {
            int w = warp_tot[lane];
            int y = w;
            #pragma unroll
            for (int off = 1; off < 32; off <<= 1) {
                int t = __shfl_up_sync(0xffffffffu, y, off);
                if (lane >= off) y += t;
            }
            warp_pref[lane] = y - w;
            if (lane == 31) s_total = y;
        }
        __syncthreads();
        int run = s_carry + warp_pref[wid] + (x - sum);
        #pragma unroll
        for (int j = 0; j < VPT; j++) {
            if (i0 + j < NN) {
                g_ptmp[i0 + j] = run;
                run += v[j];
                g_rowptr[i0 + j + 1] = run;
            }
        }
        __syncthreads();
        if (tid == 0) s_carry += s_total;
        __syncthreads();
    }
}

__global__ void k_scatter(const int* __restrict__ src, const int* __restrict__ dst) {
    int e = blockIdx.x * blockDim.x + threadIdx.x;
    if (e < NE) {
        int p = atomicAdd(&g_ptmp[dst[e]], 1);
        g_csrc[p] = src[e];
    }
}

// ---------------- feature pre-split (layer 0 input), vectorized ----------------
__global__ void k_xconv(const float* __restrict__ X) {
    int idx = blockIdx.x * blockDim.x + threadIdx.x;   // over NN*64 quads
    if (idx >= NN * 64) return;
    float4 x = *(const float4*)(X + idx * 4);
    uint32_t h0, l0, h1, l1;
    cvt_split(make_float2(x.x, x.y), h0, l0);
    cvt_split(make_float2(x.z, x.w), h1, l1);
    uint4 r;
    r.x = h0; r.y = l0; r.z = h1; r.w = l1;
    *(uint4*)(g_Xs + idx * 2) = r;
}

// ---------------- W pre-split: fp32 -> (hi,lo) bf16x2, [n][D/2] ----------------
// W layout [H, D, 64]; output col n maps to (h = n/64, k = n%64).
template <int D, int OUT, int L>
__global__ void k_wconv(const float* __restrict__ W) {
    uint2* Bs = (L == 0) ? g_Bs0 : (L == 1) ? g_Bs1 : g_Bsf;
    int idx = blockIdx.x * blockDim.x + threadIdx.x;   // over OUT*(D/2)
    if (idx >= OUT * (D / 2)) return;
    int n = idx / (D / 2), p = idx % (D / 2);
    int k = 2 * p;
    float x0 = W[(n >> 6) * (D * 64) + k * 64 + (n & 63)];
    float x1 = W[(n >> 6) * (D * 64) + (k + 1) * 64 + (n & 63)];
    uint32_t h, l;
    cvt_split(make_float2(x0, x1), h, l);
    Bs[idx] = make_uint2(h, l);
}

// ---------------- attn logit init: g_A1/g_A2 = biases ----------------
template <int H>
__global__ void k_attn_init(const float* __restrict__ bl, const float* __restrict__ br) {
    int i = blockIdx.x * blockDim.x + threadIdx.x;     // over NN*H
    if (i >= NN * H) return;
    int h = i % H;
    g_A1[i] = bl[h];
    g_A2[i] = br[h];
}

// ---------------- GEMM via mma.sync + fused attention partials ----------------
// CTA: 256 threads = 8 warps, 64-row tile. OUT=128: warp = 32r x 32c (WM=2).
// OUT=64: warp = 16r x 32c (WM=1). No smem, no syncs; inner loop is pure
// LDG.64 + HMMA.  acc = Ah@Bh + Ah@Bl + Al@Bh (lo*lo dropped, ~2^-16 rel).
// Epilogue also accumulates al/ar dot-products per row into g_A1/g_A2
// (pre-initialized to biases) via quad-reduce + atomicAdd.
// SP = pairs per activation row in g_Xs; H = heads (head = col/64).
template <int D, int OUT, int SP, int L, int H>
__global__ void __launch_bounds__(256) k_gemm_mma(const float* __restrict__ Bias,
                                                  const float* __restrict__ AL,
                                                  const float* __restrict__ AR) {
    constexpr int WN = 4;                 // n8 tiles per warp (32 cols)
    constexpr int WC = OUT / 32;          // warps along cols
    constexpr int WR = 8 / WC;            // warps along rows
    constexpr int WM = 64 / (WR * 16);    // m16 tiles per warp

    const uint2* __restrict__ Bs = (L == 0) ? g_Bs0 : (L == 1) ? g_Bs1 : g_Bsf;

    int tid = threadIdx.x, wid = tid >> 5, lane = tid & 31;
    int wr = wid / WC, wc = wid % WC;
    int rowBase = blockIdx.x * 64 + wr * (WM * 16);
    int colBase = wc * 32;
    int head = colBase >> 6;              // all 32 cols of a warp share a head
    int tq = lane >> 2, tr = lane & 3;

    float acc[WM][WN][4];
    #pragma unroll
    for (int m = 0; m < WM; m++)
        #pragma unroll
        for (int n = 0; n < WN; n++)
            #pragma unroll
            for (int i = 0; i < 4; i++) acc[m][n][i] = 0.f;

    for (int kp0 = 0; kp0 < D / 2; kp0 += 8) {        // 16 k's per step
        uint32_t bh[WN][2], bl[WN][2];
        #pragma unroll
        for (int n = 0; n < WN; n++) {
            const uint2* bp = Bs + (colBase + n * 8 + tq) * (D / 2) + kp0 + tr;
            uint2 u0 = bp[0], u1 = bp[4];
            bh[n][0] = u0.x; bl[n][0] = u0.y;
            bh[n][1] = u1.x; bl[n][1] = u1.y;
        }
        #pragma unroll
        for (int m = 0; m < WM; m++) {
            int r0 = rowBase + m * 16 + tq;
            int r1 = r0 + 8;
            const uint2* p0 = g_Xs + r0 * SP + kp0 + tr;
            const uint2* p1 = g_Xs + r1 * SP + kp0 + tr;
            uint2 z = make_uint2(0u, 0u);
            uint2 q00 = (r0 < NN) ? p0[0] : z;
            uint2 q01 = (r0 < NN) ? p0[4] : z;
            uint2 q10 = (r1 < NN) ? p1[0] : z;
            uint2 q11 = (r1 < NN) ? p1[4] : z;
            uint32_t ah[4] = {q00.x, q10.x, q01.x, q11.x};
            uint32_t al[4] = {q00.y, q10.y, q01.y, q11.y};
            #pragma unroll
            for (int n = 0; n < WN; n++) {
                mma_bf16(acc[m][n], ah, bh[n]);
                mma_bf16(acc[m][n], ah, bl[n]);
                mma_bf16(acc[m][n], al, bh[n]);
            }
        }
    }

    // epilogue: store ft + accumulate attention partials
    #pragma unroll
    for (int m = 0; m < WM; m++) {
        int r0 = rowBase + m * 16 + tq;
        int r1 = r0 + 8;
        float p1r0 = 0.f, p2r0 = 0.f, p1r1 = 0.f, p2r1 = 0.f;
        #pragma unroll
        for (int n = 0; n < WN; n++) {
            int c = colBase + n * 8 + tr * 2;
            float bA = Bias[c], bB = Bias[c + 1];
            float alc = AL[c], alc1 = AL[c + 1];
            float arc = AR[c], arc1 = AR[c + 1];
            float v0 = acc[m][n][0] + bA, v1 = acc[m][n][1] + bB;
            float v2 = acc[m][n][2] + bA, v3 = acc[m][n][3] + bB;
            if (r0 < NN) *(float2*)(g_FT + r0 * OUT + c) = make_float2(v0, v1);
            if (r1 < NN) *(float2*)(g_FT + r1 * OUT + c) = make_float2(v2, v3);
            p1r0 += v0 * alc + v1 * alc1;
            p2r0 += v0 * arc + v1 * arc1;
            p1r1 += v2 * alc + v3 * alc1;
            p2r1 += v2 * arc + v3 * arc1;
        }
        // reduce across the quad (tr = lane&3; xor 1,2 stay within quad)
        #pragma unroll
        for (int o = 1; o <= 2; o <<= 1) {
            p1r0 += __shfl_xor_sync(0xffffffffu, p1r0, o);
            p2r0 += __shfl_xor_sync(0xffffffffu, p2r0, o);
            p1r1 += __shfl_xor_sync(0xffffffffu, p1r1, o);
            p2r1 += __shfl_xor_sync(0xffffffffu, p2r1, o);
        }
        if (tr == 0) {
            if (r0 < NN) {
                atomicAdd(&g_A1[r0 * H + head], p1r0);
                atomicAdd(&g_A2[r0 * H + head], p2r0);
            }
            if (r1 < NN) {
                atomicAdd(&g_A1[r1 * H + head], p1r1);
                atomicAdd(&g_A2[r1 * H + head], p2r1);
            }
        }
    }
}

// ---------------- edge softmax + aggregation + elu ----------------
// one warp per (node, head); lane handles adjacent cols (2*lane, 2*lane+1).
// First 64 edges' (src, s) cached in registers between the two passes.
// EXT == false: writes pre-split bf16 (hi,lo) packs into g_Xs (stride 64 pairs).
// EXT == true: writes fp32 to outp.
template <int H, bool EXT>
__global__ void k_edge(float* __restrict__ outp) {
    int gw = (blockIdx.x * blockDim.x + threadIdx.x) >> 5;
    int lane = threadIdx.x & 31;
    if (gw >= NN * H) return;
    int n = gw / H, h = gw % H;
    int s0 = g_rowptr[n], s1 = g_rowptr[n + 1];
    if (s0 == s1) {
        if (EXT) *(float2*)(outp + n * 64 + 2 * lane) = make_float2(0.f, 0.f);
        else     g_Xs[n * 64 + h * 32 + lane] = make_uint2(0u, 0u);
        return;
    }

    float a1 = g_A1[n * H + h];

    // pass 1: segment max; cache first two chunks in registers
    int  si0 = 0, si1 = 0;
    float sv0 = 0.f, sv1 = 0.f;
    float m = -INFINITY;
    {
        int i = s0 + lane;
        if (i < s1) {
            si0 = g_csrc[i];
            float s = a1 + g_A2[si0 * H + h];
            sv0 = s > 0.f ? s : 0.01f * s;
            m = sv0;
        }
        i = s0 + 32 + lane;
        if (i < s1) {
            si1 = g_csrc[i];
            float s = a1 + g_A2[si1 * H + h];
            sv1 = s > 0.f ? s : 0.01f * s;
            m = fmaxf(m, sv1);
        }
        for (i = s0 + 64 + lane; i < s1; i += 32) {
            float s = a1 + g_A2[g_csrc[i] * H + h];
            s = s > 0.f ? s : 0.01f * s;
            m = fmaxf(m, s);
        }
    }
    #pragma unroll
    for (int o2 = 16; o2; o2 >>= 1) m = fmaxf(m, __shfl_xor_sync(0xffffffffu, m, o2));

    // pass 2: fused exp / denom / weighted gather-accumulate
    float acc0 = 0.f, acc1 = 0.f, den = 0.f;
    int chunk = 0;
    for (int base = s0; base < s1; base += 32, chunk++) {
        int i = base + lane;
        float e = 0.f; int si = 0;
        if (i < s1) {
            if (chunk == 0)      { si = si0; e = __expf(sv0 - m); }
            else if (chunk == 1) { si = si1; e = __expf(sv1 - m); }
            else {
                si = g_csrc[i];
                float s = a1 + g_A2[si * H + h];
                s = s > 0.f ? s : 0.01f * s;
                e = __expf(s - m);
            }
        }
        den += e;
        int cnt = min(32, s1 - base);
        for (int j = 0; j < cnt; j++) {
            float ej = __shfl_sync(0xffffffffu, e, j);
            int   sj = __shfl_sync(0xffffffffu, si, j);
            float2 fv = *(const float2*)(g_FT + sj * (H * 64) + h * 64 + 2 * lane);
            acc0 += ej * fv.x;
            acc1 += ej * fv.y;
        }
    }
    #pragma unroll
    for (int o2 = 16; o2; o2 >>= 1) den += __shfl_xor_sync(0xffffffffu, den, o2);

    float r0 = acc0 / den, r1 = acc1 / den;
    r0 = r0 > 0.f ? r0 : (__expf(r0) - 1.f);   // elu
    r1 = r1 > 0.f ? r1 : (__expf(r1) - 1.f);
    if (EXT) {
        *(float2*)(outp + n * 64 + 2 * lane) = make_float2(r0, r1);
    } else {
        uint32_t hp, lp;
        cvt_split(make_float2(r0, r1), hp, lp);
        g_Xs[n * 64 + h * 32 + lane] = make_uint2(hp, lp);
    }
}

// ---------------- launch ----------------
extern "C" void kernel_launch(void* const* d_in, const int* in_sizes, int n_in,
                              void* d_out, int out_size) {
    const float* features = (const float*)d_in[0];
    const int*   src = (const int*)d_in[1];
    const int*   dst = (const int*)d_in[2];
    const float* W0  = (const float*)d_in[3];
    const float* b0  = (const float*)d_in[4];
    const float* al0 = (const float*)d_in[5];
    const float* bl0 = (const float*)d_in[6];
    const float* ar0 = (const float*)d_in[7];
    const float* br0 = (const float*)d_in[8];
    const float* W1  = (const float*)d_in[9];
    const float* b1  = (const float*)d_in[10];
    const float* al1 = (const float*)d_in[11];
    const float* bl1 = (const float*)d_in[12];
    const float* ar1 = (const float*)d_in[13];
    const float* br1 = (const float*)d_in[14];
    const float* Wf  = (const float*)d_in[15];
    const float* bf  = (const float*)d_in[16];
    const float* alf = (const float*)d_in[17];
    const float* blf = (const float*)d_in[18];
    const float* arf = (const float*)d_in[19];
    const float* brf = (const float*)d_in[20];
    float* out = (float*)d_out;

    // pre-split conversions
    k_wconv<256, 128, 0><<<(128 * 128 + 255) / 256, 256>>>(W0);
    k_wconv<128, 128, 1><<<(128 * 64 + 255) / 256, 256>>>(W1);
    k_wconv<128, 64, 2><<<(64 * 64 + 255) / 256, 256>>>(Wf);
    k_xconv<<<(NN * 64 + 255) / 256, 256>>>(features);

    // CSR build (graph shared by all three layers)
    k_zero_deg<<<(NN + 255) / 256, 256>>>();
    k_count<<<(NE + 255) / 256, 256>>>(dst);
    k_scan<<<1, 1024>>>();
    k_scatter<<<(NE + 255) / 256, 256>>>(src, dst);

    const int gemm_blocks = (NN + 63) / 64;            // 782
    const int init_h2 = (NN * 2 + 255) / 256;
    const int init_h1 = (NN + 255) / 256;
    const int edge_blocks_h2 = (NN * 2 + 7) / 8;
    const int edge_blocks_h1 = (NN + 7) / 8;

    // ---- layer 0: IN=256 -> [N, 128] ----
    k_attn_init<2><<<init_h2, 256>>>(bl0, br0);
    k_gemm_mma<256, 128, 128, 0, 2><<<gemm_blocks, 256>>>(b0, al0, ar0);
    k_edge<2, false><<<edge_blocks_h2, 256>>>(nullptr);

    // ---- layer 1: 128 -> [N, 128] ----
    k_attn_init<2><<<init_h2, 256>>>(bl1, br1);
    k_gemm_mma<128, 128, 64, 1, 2><<<gemm_blocks, 256>>>(b1, al1, ar1);
    k_edge<2, false><<<edge_blocks_h2, 256>>>(nullptr);

    // ---- final layer: 128 -> [N, 64] (H=1) ----
    k_attn_init<1><<<init_h1, 256>>>(blf, brf);
    k_gemm_mma<128, 64, 64, 2, 1><<<gemm_blocks, 256>>>(bf, alf, arf);
    k_edge<1, true><<<edge_blocks_h1, 256>>>(out);
}